// round 9
// baseline (speedup 1.0000x reference)
#include <cuda_runtime.h>
#include <math.h>

#define N_NODES   100000
#define N_EDGES   1000000
#define HID       64
#define OUT_DIM   32
#define NUM_GRAPHS 512

#define SCAN_BS 1024
#define SCAN_NB ((N_NODES + SCAN_BS - 1) / SCAN_BS)   // 98

// ---------------- device scratch (zero-initialized at module load; ----------
// ---------------- g_deg and g_sums are re-zeroed by their consumers) --------
__device__ float g_agg[N_NODES * HID];
__device__ float g_h[N_NODES * HID];
__device__ float g_sums[NUM_GRAPHS * HID];     // invariant: zero between launches
__device__ float g_Wc[HID * OUT_DIM];
__device__ float g_bc[OUT_DIM];
__device__ int   g_batch[N_NODES];
__device__ int   g_deg[N_NODES];               // invariant: zero between launches
__device__ int   g_rowptr[N_NODES + 1];
__device__ int   g_pos[N_NODES];
__device__ int   g_csr_src[N_EDGES];
__device__ int   g_blocksum[SCAN_NB];

// ---------------- packed f32x2 helpers --------------------------------------
__device__ __forceinline__ void fma2(unsigned long long& d, unsigned long long a,
                                     unsigned long long b) {
    asm("fma.rn.f32x2 %0, %1, %2, %0;" : "+l"(d) : "l"(a), "l"(b));
}
__device__ __forceinline__ float2 unpack2(unsigned long long v) {
    float lo, hi;
    asm("mov.b64 {%0,%1}, %2;" : "=f"(lo), "=f"(hi) : "l"(v));
    return make_float2(lo, hi);
}
__device__ __forceinline__ unsigned long long pack2(float lo, float hi) {
    unsigned long long r;
    asm("mov.b64 %0, {%1,%2};" : "=l"(r) : "f"(lo), "f"(hi));
    return r;
}
__device__ __forceinline__ void red_add_f32(float* addr, float v) {
    asm volatile("red.global.add.f32 [%0], %1;" :: "l"(addr), "f"(v) : "memory");
}

// ---------------- dtype-agnostic index access --------------------------------
__device__ __forceinline__ int load_idx(const void* buf, int i, int is64) {
    return is64 ? (int)((const long long*)buf)[i] : ((const int*)buf)[i];
}
// per-warp int64 detection: sample 32 odd int32 words of the edge buffer.
// int64 indices (<2^31) have zero high words; int32 data makes them random
// node ids (P[all 32 zero] ~ 1e-160).
__device__ __forceinline__ int detect_is64(const int* ei32) {
    int lane = threadIdx.x & 31;
    int w = __ldg(&ei32[2 * lane + 1]);
    return __all_sync(0xffffffffu, w == 0) ? 1 : 0;
}

// ---------------- prep: hist + batch repack + head-weight fusion -------------
__global__ void k_prep(const int* __restrict__ ei32, const void* __restrict__ eiv,
                       const void* __restrict__ bv,
                       const float* __restrict__ Wp1, const float* __restrict__ bp1,
                       const float* __restrict__ Wp2, const float* __restrict__ bp2) {
    int is64 = detect_is64(ei32);
    int i = blockIdx.x * blockDim.x + threadIdx.x;
    if (i < N_EDGES) {
        int d = load_idx(eiv, N_EDGES + i, is64);
        atomicAdd(&g_deg[d], 1);
    }
    if (i < N_NODES) {
        g_batch[i] = load_idx(bv, i, is64);
    }
    if (i < HID * OUT_DIM) {
        int k = i >> 5, c = i & 31;
        float s = 0.0f;
        for (int m = 0; m < HID; m++) s += Wp1[k * HID + m] * Wp2[m * OUT_DIM + c];
        g_Wc[i] = s;
    } else if (i < HID * OUT_DIM + OUT_DIM) {
        int c = i - HID * OUT_DIM;
        float s = bp2[c];
        for (int m = 0; m < HID; m++) s += bp1[m] * Wp2[m * OUT_DIM + c];
        g_bc[c] = s;
    }
}

// ---------------- scan pass 1: block-local exclusive scan (re-zeroes deg) ----
__global__ void __launch_bounds__(SCAN_BS) k_scan_block() {
    __shared__ int sh[SCAN_BS];
    const int t = threadIdx.x;
    const int i = blockIdx.x * SCAN_BS + t;
    int v = 0;
    if (i < N_NODES) {
        v = g_deg[i];
        g_deg[i] = 0;              // restore zero-invariant for next launch
    }
    sh[t] = v;
    __syncthreads();
    #pragma unroll
    for (int off = 1; off < SCAN_BS; off <<= 1) {
        int u = (t >= off) ? sh[t - off] : 0;
        __syncthreads();
        sh[t] += u;
        __syncthreads();
    }
    if (i < N_NODES) g_rowptr[i] = sh[t] - v;
    if (t == SCAN_BS - 1) g_blocksum[blockIdx.x] = sh[t];
}

// ---------------- scan pass 2: per-block redundant top scan + add ------------
__global__ void __launch_bounds__(256) k_scan_add() {
    __shared__ int sh[128];
    const int t = threadIdx.x;
    if (t < 128) sh[t] = (t < SCAN_NB) ? g_blocksum[t] : 0;
    __syncthreads();
    #pragma unroll
    for (int off = 1; off < 128; off <<= 1) {
        int v = (t < 128 && t >= off) ? sh[t - off] : 0;
        __syncthreads();
        if (t < 128) sh[t] += v;
        __syncthreads();
    }
    int chunk = blockIdx.x >> 2;
    int boff = (chunk == 0) ? 0 : sh[chunk - 1];
    int i = blockIdx.x * 256 + t;
    if (i < N_NODES) {
        int v = g_rowptr[i] + boff;
        g_rowptr[i] = v;
        g_pos[i] = v;
    }
    if (blockIdx.x == 0 && t == 0) g_rowptr[N_NODES] = sh[SCAN_NB - 1];
}

// ---------------- fill CSR ----------------------------------------------------
__global__ void k_fill(const int* __restrict__ ei32, const void* __restrict__ eiv) {
    int is64 = detect_is64(ei32);
    int e = blockIdx.x * blockDim.x + threadIdx.x;
    if (e >= N_EDGES) return;
    int s = load_idx(eiv, e, is64);
    int d = load_idx(eiv, N_EDGES + e, is64);
    int p = atomicAdd(&g_pos[d], 1);
    g_csr_src[p] = s;
}

// ---------------- gather: agg[n] = self[n] + sum_{j->n} feat[j] ---------------
template <bool USE_H>
__global__ void k_gather(const float* __restrict__ x) {
    int idx = blockIdx.x * blockDim.x + threadIdx.x;
    if (idx >= N_NODES * 16) return;
    int node = idx >> 4;
    int c = idx & 15;
    const float* feat = USE_H ? g_h : x;

    float4 acc = __ldg(reinterpret_cast<const float4*>(feat + (size_t)node * HID) + c);
    int p = g_rowptr[node];
    int pe = g_rowptr[node + 1];
    for (; p < pe; p++) {
        int s = __ldg(&g_csr_src[p]);
        float4 v = __ldg(reinterpret_cast<const float4*>(feat + (size_t)s * HID) + c);
        acc.x += v.x; acc.y += v.y; acc.z += v.z; acc.w += v.w;
    }
    *(reinterpret_cast<float4*>(g_agg + (size_t)node * HID) + c) = acc;
}

// ---------------- fused GIN MLP with packed f32x2 FMA -------------------------
template <int MODE>
__global__ void __launch_bounds__(128) k_mlp(
    const float* __restrict__ W1, const float* __restrict__ b1,
    const float* __restrict__ W2, const float* __restrict__ b2,
    float* __restrict__ emb_out)
{
    __shared__ __align__(16) float A[64 * 66];
    __shared__ __align__(16) unsigned long long WT[64 * 33];
    const int t = threadIdx.x;
    const int base = blockIdx.x * 64;
    const int cg = t & 15;
    const int ng = t >> 4;

    #pragma unroll
    for (int it = 0; it < 8; it++) {
        int L4 = t + 128 * it;
        int row = L4 >> 4, c4 = L4 & 15;
        int node = base + row;
        float4 v = make_float4(0.f, 0.f, 0.f, 0.f);
        if (node < N_NODES)
            v = __ldg(reinterpret_cast<const float4*>(g_agg + (size_t)node * HID) + c4);
        float* p = A + row * 66 + c4 * 4;
        p[0] = v.x; p[1] = v.y; p[2] = v.z; p[3] = v.w;
    }
    #pragma unroll
    for (int it = 0; it < 16; it++) {
        int idx = t + 128 * it;
        int c = idx & 63, k2 = idx >> 6;
        float w0 = __ldg(W1 + (2 * k2) * HID + c);
        float w1 = __ldg(W1 + (2 * k2 + 1) * HID + c);
        WT[c * 33 + k2] = pack2(w0, w1);
    }
    __syncthreads();

    unsigned long long acc2[8][4];
    #pragma unroll
    for (int r = 0; r < 8; r++)
        #pragma unroll
        for (int j = 0; j < 4; j++) acc2[r][j] = 0ULL;

    #pragma unroll 4
    for (int k2 = 0; k2 < 32; k2++) {
        unsigned long long w0 = WT[(cg +  0) * 33 + k2];
        unsigned long long w1 = WT[(cg + 16) * 33 + k2];
        unsigned long long w2 = WT[(cg + 32) * 33 + k2];
        unsigned long long w3 = WT[(cg + 48) * 33 + k2];
        #pragma unroll
        for (int r = 0; r < 8; r++) {
            unsigned long long a2 =
                *reinterpret_cast<const unsigned long long*>(A + (ng * 8 + r) * 66 + 2 * k2);
            fma2(acc2[r][0], a2, w0);
            fma2(acc2[r][1], a2, w1);
            fma2(acc2[r][2], a2, w2);
            fma2(acc2[r][3], a2, w3);
        }
    }

    float bias[4];
    #pragma unroll
    for (int j = 0; j < 4; j++) bias[j] = __ldg(b1 + cg + 16 * j);

    __syncthreads();

    #pragma unroll
    for (int r = 0; r < 8; r++) {
        #pragma unroll
        for (int j = 0; j < 4; j++) {
            float2 p = unpack2(acc2[r][j]);
            A[(ng * 8 + r) * 66 + cg + 16 * j] = fmaxf(p.x + p.y + bias[j], 0.0f);
            acc2[r][j] = 0ULL;
        }
    }
    #pragma unroll
    for (int it = 0; it < 16; it++) {
        int idx = t + 128 * it;
        int c = idx & 63, k2 = idx >> 6;
        float w0 = __ldg(W2 + (2 * k2) * HID + c);
        float w1 = __ldg(W2 + (2 * k2 + 1) * HID + c);
        WT[c * 33 + k2] = pack2(w0, w1);
    }
    __syncthreads();

    #pragma unroll 4
    for (int k2 = 0; k2 < 32; k2++) {
        unsigned long long w0 = WT[(cg +  0) * 33 + k2];
        unsigned long long w1 = WT[(cg + 16) * 33 + k2];
        unsigned long long w2 = WT[(cg + 32) * 33 + k2];
        unsigned long long w3 = WT[(cg + 48) * 33 + k2];
        #pragma unroll
        for (int r = 0; r < 8; r++) {
            unsigned long long a2 =
                *reinterpret_cast<const unsigned long long*>(A + (ng * 8 + r) * 66 + 2 * k2);
            fma2(acc2[r][0], a2, w0);
            fma2(acc2[r][1], a2, w1);
            fma2(acc2[r][2], a2, w2);
            fma2(acc2[r][3], a2, w3);
        }
    }

    #pragma unroll
    for (int j = 0; j < 4; j++) bias[j] = __ldg(b2 + cg + 16 * j);

    #pragma unroll
    for (int r = 0; r < 8; r++) {
        int node = base + ng * 8 + r;
        if (node >= N_NODES) continue;
        if (MODE == 0) {
            #pragma unroll
            for (int j = 0; j < 4; j++) {
                float2 p = unpack2(acc2[r][j]);
                float v = fmaxf(p.x + p.y + bias[j], 0.0f);
                g_h[(size_t)node * HID + cg + 16 * j] = v;
            }
        } else {
            int gidx = g_batch[node];
            #pragma unroll
            for (int j = 0; j < 4; j++) {
                float2 p = unpack2(acc2[r][j]);
                float v = p.x + p.y + bias[j];
                int col = cg + 16 * j;
                emb_out[(size_t)node * HID + col] = v;
                red_add_f32(g_sums + (size_t)gidx * HID + col, fmaxf(v, 0.0f));
            }
        }
    }
}

// ---------------- final head (re-zeroes g_sums after use) --------------------
__global__ void k_final(float* __restrict__ outp) {
    int g = blockIdx.x * blockDim.x + threadIdx.x;
    if (g >= NUM_GRAPHS) return;
    int l0, l1;
    {
        int v = g;
        int a = 0, b = N_NODES;
        while (a < b) { int m = (a + b) >> 1; if (g_batch[m] < v) a = m + 1; else b = m; }
        l0 = a;
        v = g + 1; a = l0; b = N_NODES;
        while (a < b) { int m = (a + b) >> 1; if (g_batch[m] < v) a = m + 1; else b = m; }
        l1 = a;
    }
    float cnt = (float)(l1 - l0);
    float inv = 1.0f / fmaxf(cnt, 1.0f);

    float acc[OUT_DIM];
    #pragma unroll
    for (int c = 0; c < OUT_DIM; c++) acc[c] = g_bc[c];
    for (int k = 0; k < HID; k++) {
        float p = g_sums[g * HID + k] * inv;
        g_sums[g * HID + k] = 0.0f;          // restore zero-invariant
        #pragma unroll
        for (int c = 0; c < OUT_DIM; c++) acc[c] += p * g_Wc[k * OUT_DIM + c];
    }
    float m = acc[0];
    #pragma unroll
    for (int c = 1; c < OUT_DIM; c++) m = fmaxf(m, acc[c]);
    float s = 0.0f;
    #pragma unroll
    for (int c = 0; c < OUT_DIM; c++) s += expf(acc[c] - m);
    float ls = logf(s) + m;
    #pragma unroll
    for (int c = 0; c < OUT_DIM; c++) outp[g * OUT_DIM + c] = acc[c] - ls;
}

// ---------------- host launch ----------------------------------------------------
extern "C" void kernel_launch(void* const* d_in, const int* in_sizes, int n_in,
                              void* d_out, int out_size) {
    const float* x     = (const float*)d_in[0];
    const void*  ei    = d_in[1];
    const void*  batch = d_in[2];
    const float* W1a = (const float*)d_in[3];
    const float* b1a = (const float*)d_in[4];
    const float* W2a = (const float*)d_in[5];
    const float* b2a = (const float*)d_in[6];
    const float* W1b = (const float*)d_in[7];
    const float* b1b = (const float*)d_in[8];
    const float* W2b = (const float*)d_in[9];
    const float* b2b = (const float*)d_in[10];
    const float* Wp1 = (const float*)d_in[11];
    const float* bp1 = (const float*)d_in[12];
    const float* Wp2 = (const float*)d_in[13];
    const float* bp2 = (const float*)d_in[14];

    float* out     = (float*)d_out;
    float* emb_out = out;
    float* lsm_out = out + (size_t)N_NODES * HID;

    const int mlp_blocks    = (N_NODES + 63) / 64;
    const int gather_blocks = (N_NODES * 16 + 255) / 256;

    k_prep<<<(N_EDGES + 255) / 256, 256>>>((const int*)ei, ei, batch, Wp1, bp1, Wp2, bp2);
    k_scan_block<<<SCAN_NB, SCAN_BS>>>();
    k_scan_add<<<(N_NODES + 255) / 256, 256>>>();
    k_fill<<<(N_EDGES + 255) / 256, 256>>>((const int*)ei, ei);

    // layer 0
    k_gather<false><<<gather_blocks, 256>>>(x);
    k_mlp<0><<<mlp_blocks, 128>>>(W1a, b1a, W2a, b2a, nullptr);

    // layer 1
    k_gather<true><<<gather_blocks, 256>>>(x);
    k_mlp<1><<<mlp_blocks, 128>>>(W1b, b1b, W2b, b2b, emb_out);

    k_final<<<(NUM_GRAPHS + 127) / 128, 128>>>(lsm_out);
}

// round 10
// speedup vs baseline: 1.0636x; 1.0636x over previous
#include <cuda_runtime.h>
#include <math.h>

#define N_NODES   100000
#define N_EDGES   1000000
#define HID       64
#define OUT_DIM   32
#define NUM_GRAPHS 512

#define SCAN_BS 1024
#define SCAN_NB ((N_NODES + SCAN_BS - 1) / SCAN_BS)   // 98

// ---------------- device scratch -------------------------------------------
__device__ float g_agg[N_NODES * HID];
__device__ float g_h[N_NODES * HID];
__device__ float g_sums[NUM_GRAPHS * HID];
__device__ float g_Wc[HID * OUT_DIM];
__device__ float g_bc[OUT_DIM];
__device__ int   g_is64;
__device__ int   g_batch[N_NODES];
__device__ int   g_deg[N_NODES];
__device__ int   g_rowptr[N_NODES + 1];
__device__ int   g_pos[N_NODES];
__device__ int   g_csr_src[N_EDGES];
__device__ int   g_blocksum[SCAN_NB];

// ---------------- packed f32x2 helpers --------------------------------------
__device__ __forceinline__ void fma2(unsigned long long& d, unsigned long long a,
                                     unsigned long long b) {
    asm("fma.rn.f32x2 %0, %1, %2, %0;" : "+l"(d) : "l"(a), "l"(b));
}
__device__ __forceinline__ float2 unpack2(unsigned long long v) {
    float lo, hi;
    asm("mov.b64 {%0,%1}, %2;" : "=f"(lo), "=f"(hi) : "l"(v));
    return make_float2(lo, hi);
}
__device__ __forceinline__ unsigned long long pack2(float lo, float hi) {
    unsigned long long r;
    asm("mov.b64 %0, {%1,%2};" : "=l"(r) : "f"(lo), "f"(hi));
    return r;
}
__device__ __forceinline__ void red_add_f32(float* addr, float v) {
    asm volatile("red.global.add.f32 [%0], %1;" :: "l"(addr), "f"(v) : "memory");
}

// ---------------- edge index access (dtype-agnostic) -------------------------
__device__ __forceinline__ int load_idx(const void* buf, int i, int is64) {
    return is64 ? (int)((const long long*)buf)[i] : ((const int*)buf)[i];
}

// ---------------- setup: detect dtype + zero deg/sums + fuse head ------------
__global__ void k_setup(const int* __restrict__ ei32,
                        const float* __restrict__ Wp1, const float* __restrict__ bp1,
                        const float* __restrict__ Wp2, const float* __restrict__ bp2) {
    if (blockIdx.x == 0) {
        __shared__ int nz;
        if (threadIdx.x == 0) nz = 0;
        __syncthreads();
        if (ei32[2 * threadIdx.x + 1] != 0) nz = 1;   // benign race
        __syncthreads();
        if (threadIdx.x == 0) g_is64 = (nz == 0) ? 1 : 0;
    }
    int i = blockIdx.x * blockDim.x + threadIdx.x;
    if (i < N_NODES) g_deg[i] = 0;
    int j = i - N_NODES;
    if (j >= 0) {
        if (j < NUM_GRAPHS * HID) {
            g_sums[j] = 0.0f;
        } else if (j < NUM_GRAPHS * HID + HID * OUT_DIM) {
            int q = j - NUM_GRAPHS * HID;
            int k = q >> 5, c = q & 31;
            float s = 0.0f;
            for (int m = 0; m < HID; m++) s += Wp1[k * HID + m] * Wp2[m * OUT_DIM + c];
            g_Wc[q] = s;
        } else if (j < NUM_GRAPHS * HID + HID * OUT_DIM + OUT_DIM) {
            int c = j - NUM_GRAPHS * HID - HID * OUT_DIM;
            float s = bp2[c];
            for (int m = 0; m < HID; m++) s += bp1[m] * Wp2[m * OUT_DIM + c];
            g_bc[c] = s;
        }
    }
}

// ---------------- histogram dst degrees + repack batch -----------------------
__global__ void k_hist(const void* __restrict__ eiv, const void* __restrict__ bv) {
    int i = blockIdx.x * blockDim.x + threadIdx.x;
    int is64 = g_is64;
    if (i < N_EDGES) {
        int d = load_idx(eiv, N_EDGES + i, is64);
        atomicAdd(&g_deg[d], 1);
    }
    if (i < N_NODES) {
        g_batch[i] = load_idx(bv, i, is64);
    }
}

// ---------------- scan pass 1: block-local exclusive scan --------------------
__global__ void __launch_bounds__(SCAN_BS) k_scan_block() {
    __shared__ int sh[SCAN_BS];
    const int t = threadIdx.x;
    const int i = blockIdx.x * SCAN_BS + t;
    int v = (i < N_NODES) ? g_deg[i] : 0;
    sh[t] = v;
    __syncthreads();
    #pragma unroll
    for (int off = 1; off < SCAN_BS; off <<= 1) {
        int u = (t >= off) ? sh[t - off] : 0;
        __syncthreads();
        sh[t] += u;
        __syncthreads();
    }
    if (i < N_NODES) g_rowptr[i] = sh[t] - v;
    if (t == SCAN_BS - 1) g_blocksum[blockIdx.x] = sh[t];
}

// ---------------- scan pass 2: per-block redundant top scan + add ------------
__global__ void __launch_bounds__(256) k_scan_add() {
    __shared__ int sh[128];
    const int t = threadIdx.x;
    if (t < 128) sh[t] = (t < SCAN_NB) ? g_blocksum[t] : 0;
    __syncthreads();
    #pragma unroll
    for (int off = 1; off < 128; off <<= 1) {
        int v = (t < 128 && t >= off) ? sh[t - off] : 0;
        __syncthreads();
        if (t < 128) sh[t] += v;
        __syncthreads();
    }
    int chunk = blockIdx.x >> 2;                 // 256-thread block -> 1024-chunk id
    int boff = (chunk == 0) ? 0 : sh[chunk - 1];
    int i = blockIdx.x * 256 + t;
    if (i < N_NODES) {
        int v = g_rowptr[i] + boff;
        g_rowptr[i] = v;
        g_pos[i] = v;
    }
    if (blockIdx.x == 0 && t == 0) g_rowptr[N_NODES] = sh[SCAN_NB - 1];
}

// ---------------- fill CSR (reads input edge buffer directly) ----------------
__global__ void k_fill(const void* __restrict__ eiv) {
    int e = blockIdx.x * blockDim.x + threadIdx.x;
    if (e >= N_EDGES) return;
    int is64 = g_is64;
    int s = load_idx(eiv, e, is64);
    int d = load_idx(eiv, N_EDGES + e, is64);
    int p = atomicAdd(&g_pos[d], 1);
    g_csr_src[p] = s;
}

// ---------------- gather: agg[n] = self[n] + sum_{j->n} feat[j] ---------------
// 16 threads/node, float4 each; 2 edges in flight to break the L2-latency chain.
template <bool USE_H>
__global__ void k_gather(const float* __restrict__ x) {
    int idx = blockIdx.x * blockDim.x + threadIdx.x;
    if (idx >= N_NODES * 16) return;
    int node = idx >> 4;
    int c = idx & 15;
    const float* feat = USE_H ? g_h : x;

    float4 acc = __ldg(reinterpret_cast<const float4*>(feat + (size_t)node * HID) + c);
    int p  = g_rowptr[node];
    int pe = g_rowptr[node + 1];
    for (; p + 1 < pe; p += 2) {
        int s0 = __ldg(&g_csr_src[p]);
        int s1 = __ldg(&g_csr_src[p + 1]);
        float4 v0 = __ldg(reinterpret_cast<const float4*>(feat + (size_t)s0 * HID) + c);
        float4 v1 = __ldg(reinterpret_cast<const float4*>(feat + (size_t)s1 * HID) + c);
        acc.x += v0.x + v1.x; acc.y += v0.y + v1.y;
        acc.z += v0.z + v1.z; acc.w += v0.w + v1.w;
    }
    if (p < pe) {
        int s0 = __ldg(&g_csr_src[p]);
        float4 v0 = __ldg(reinterpret_cast<const float4*>(feat + (size_t)s0 * HID) + c);
        acc.x += v0.x; acc.y += v0.y; acc.z += v0.z; acc.w += v0.w;
    }
    *(reinterpret_cast<float4*>(g_agg + (size_t)node * HID) + c) = acc;
}

// ---------------- fused GIN MLP with packed f32x2 FMA -------------------------
template <int MODE>
__global__ void __launch_bounds__(128) k_mlp(
    const float* __restrict__ W1, const float* __restrict__ b1,
    const float* __restrict__ W2, const float* __restrict__ b2,
    float* __restrict__ emb_out)
{
    __shared__ __align__(16) float A[64 * 66];
    __shared__ __align__(16) unsigned long long WT[64 * 33];
    const int t = threadIdx.x;
    const int base = blockIdx.x * 64;
    const int cg = t & 15;
    const int ng = t >> 4;

    #pragma unroll
    for (int it = 0; it < 8; it++) {
        int L4 = t + 128 * it;
        int row = L4 >> 4, c4 = L4 & 15;
        int node = base + row;
        float4 v = make_float4(0.f, 0.f, 0.f, 0.f);
        if (node < N_NODES)
            v = __ldg(reinterpret_cast<const float4*>(g_agg + (size_t)node * HID) + c4);
        float* p = A + row * 66 + c4 * 4;
        p[0] = v.x; p[1] = v.y; p[2] = v.z; p[3] = v.w;
    }
    #pragma unroll
    for (int it = 0; it < 16; it++) {
        int idx = t + 128 * it;
        int c = idx & 63, k2 = idx >> 6;
        float w0 = __ldg(W1 + (2 * k2) * HID + c);
        float w1 = __ldg(W1 + (2 * k2 + 1) * HID + c);
        WT[c * 33 + k2] = pack2(w0, w1);
    }
    __syncthreads();

    unsigned long long acc2[8][4];
    #pragma unroll
    for (int r = 0; r < 8; r++)
        #pragma unroll
        for (int j = 0; j < 4; j++) acc2[r][j] = 0ULL;

    #pragma unroll 4
    for (int k2 = 0; k2 < 32; k2++) {
        unsigned long long w0 = WT[(cg +  0) * 33 + k2];
        unsigned long long w1 = WT[(cg + 16) * 33 + k2];
        unsigned long long w2 = WT[(cg + 32) * 33 + k2];
        unsigned long long w3 = WT[(cg + 48) * 33 + k2];
        #pragma unroll
        for (int r = 0; r < 8; r++) {
            unsigned long long a2 =
                *reinterpret_cast<const unsigned long long*>(A + (ng * 8 + r) * 66 + 2 * k2);
            fma2(acc2[r][0], a2, w0);
            fma2(acc2[r][1], a2, w1);
            fma2(acc2[r][2], a2, w2);
            fma2(acc2[r][3], a2, w3);
        }
    }

    float bias[4];
    #pragma unroll
    for (int j = 0; j < 4; j++) bias[j] = __ldg(b1 + cg + 16 * j);

    __syncthreads();

    #pragma unroll
    for (int r = 0; r < 8; r++) {
        #pragma unroll
        for (int j = 0; j < 4; j++) {
            float2 p = unpack2(acc2[r][j]);
            A[(ng * 8 + r) * 66 + cg + 16 * j] = fmaxf(p.x + p.y + bias[j], 0.0f);
            acc2[r][j] = 0ULL;
        }
    }
    #pragma unroll
    for (int it = 0; it < 16; it++) {
        int idx = t + 128 * it;
        int c = idx & 63, k2 = idx >> 6;
        float w0 = __ldg(W2 + (2 * k2) * HID + c);
        float w1 = __ldg(W2 + (2 * k2 + 1) * HID + c);
        WT[c * 33 + k2] = pack2(w0, w1);
    }
    __syncthreads();

    #pragma unroll 4
    for (int k2 = 0; k2 < 32; k2++) {
        unsigned long long w0 = WT[(cg +  0) * 33 + k2];
        unsigned long long w1 = WT[(cg + 16) * 33 + k2];
        unsigned long long w2 = WT[(cg + 32) * 33 + k2];
        unsigned long long w3 = WT[(cg + 48) * 33 + k2];
        #pragma unroll
        for (int r = 0; r < 8; r++) {
            unsigned long long a2 =
                *reinterpret_cast<const unsigned long long*>(A + (ng * 8 + r) * 66 + 2 * k2);
            fma2(acc2[r][0], a2, w0);
            fma2(acc2[r][1], a2, w1);
            fma2(acc2[r][2], a2, w2);
            fma2(acc2[r][3], a2, w3);
        }
    }

    #pragma unroll
    for (int j = 0; j < 4; j++) bias[j] = __ldg(b2 + cg + 16 * j);

    #pragma unroll
    for (int r = 0; r < 8; r++) {
        int node = base + ng * 8 + r;
        if (node >= N_NODES) continue;
        if (MODE == 0) {
            #pragma unroll
            for (int j = 0; j < 4; j++) {
                float2 p = unpack2(acc2[r][j]);
                float v = fmaxf(p.x + p.y + bias[j], 0.0f);
                g_h[(size_t)node * HID + cg + 16 * j] = v;
            }
        } else {
            int gidx = g_batch[node];
            #pragma unroll
            for (int j = 0; j < 4; j++) {
                float2 p = unpack2(acc2[r][j]);
                float v = p.x + p.y + bias[j];
                int col = cg + 16 * j;
                emb_out[(size_t)node * HID + col] = v;
                red_add_f32(g_sums + (size_t)gidx * HID + col, fmaxf(v, 0.0f));
            }
        }
    }
}

// ---------------- final head ---------------------------------------------------
__global__ void k_final(float* __restrict__ outp) {
    int g = blockIdx.x * blockDim.x + threadIdx.x;
    if (g >= NUM_GRAPHS) return;
    int l0, l1;
    {
        int v = g;
        int a = 0, b = N_NODES;
        while (a < b) { int m = (a + b) >> 1; if (g_batch[m] < v) a = m + 1; else b = m; }
        l0 = a;
        v = g + 1; a = l0; b = N_NODES;
        while (a < b) { int m = (a + b) >> 1; if (g_batch[m] < v) a = m + 1; else b = m; }
        l1 = a;
    }
    float cnt = (float)(l1 - l0);
    float inv = 1.0f / fmaxf(cnt, 1.0f);

    float acc[OUT_DIM];
    #pragma unroll
    for (int c = 0; c < OUT_DIM; c++) acc[c] = g_bc[c];
    for (int k = 0; k < HID; k++) {
        float p = g_sums[g * HID + k] * inv;
        #pragma unroll
        for (int c = 0; c < OUT_DIM; c++) acc[c] += p * g_Wc[k * OUT_DIM + c];
    }
    float m = acc[0];
    #pragma unroll
    for (int c = 1; c < OUT_DIM; c++) m = fmaxf(m, acc[c]);
    float s = 0.0f;
    #pragma unroll
    for (int c = 0; c < OUT_DIM; c++) s += expf(acc[c] - m);
    float ls = logf(s) + m;
    #pragma unroll
    for (int c = 0; c < OUT_DIM; c++) outp[g * OUT_DIM + c] = acc[c] - ls;
}

// ---------------- host launch ----------------------------------------------------
extern "C" void kernel_launch(void* const* d_in, const int* in_sizes, int n_in,
                              void* d_out, int out_size) {
    const float* x     = (const float*)d_in[0];
    const void*  ei    = d_in[1];
    const void*  batch = d_in[2];
    const float* W1a = (const float*)d_in[3];
    const float* b1a = (const float*)d_in[4];
    const float* W2a = (const float*)d_in[5];
    const float* b2a = (const float*)d_in[6];
    const float* W1b = (const float*)d_in[7];
    const float* b1b = (const float*)d_in[8];
    const float* W2b = (const float*)d_in[9];
    const float* b2b = (const float*)d_in[10];
    const float* Wp1 = (const float*)d_in[11];
    const float* bp1 = (const float*)d_in[12];
    const float* Wp2 = (const float*)d_in[13];
    const float* bp2 = (const float*)d_in[14];

    float* out     = (float*)d_out;
    float* emb_out = out;
    float* lsm_out = out + (size_t)N_NODES * HID;

    const int mlp_blocks    = (N_NODES + 63) / 64;
    const int gather_blocks = (N_NODES * 16 + 255) / 256;
    const int setup_n       = N_NODES + NUM_GRAPHS * HID + HID * OUT_DIM + OUT_DIM;

    k_setup<<<(setup_n + 255) / 256, 256>>>((const int*)ei, Wp1, bp1, Wp2, bp2);
    k_hist<<<(N_EDGES + 255) / 256, 256>>>(ei, batch);
    k_scan_block<<<SCAN_NB, SCAN_BS>>>();
    k_scan_add<<<(N_NODES + 255) / 256, 256>>>();
    k_fill<<<(N_EDGES + 255) / 256, 256>>>(ei);

    // layer 0
    k_gather<false><<<gather_blocks, 256>>>(x);
    k_mlp<0><<<mlp_blocks, 128>>>(W1a, b1a, W2a, b2a, nullptr);

    // layer 1
    k_gather<true><<<gather_blocks, 256>>>(x);
    k_mlp<1><<<mlp_blocks, 128>>>(W1b, b1b, W2b, b2b, emb_out);

    k_final<<<(NUM_GRAPHS + 127) / 128, 128>>>(lsm_out);
}